// round 6
// baseline (speedup 1.0000x reference)
#include <cuda_runtime.h>

#define IN_F   4096
#define OUT_F  4096
#define BATCH  16384
#define NSPLIT 256         // row-splits for W column-sum partials

// Scratch (no device allocation allowed) — fully overwritten every launch
// sequence, so graph replays are deterministic.
__device__ float g_partial[NSPLIT * IN_F];   // 4 MB (L2-resident)
__device__ float g_ws[IN_F];
__device__ float g_bsum;

// ---------------------------------------------------------------------------
// A1: partial column sums of W.
// tid -> (split, colgroup-of-4). Consecutive threads hit consecutive float4s
// within a row -> perfectly coalesced. Each thread walks OUT_F/NSPLIT = 16
// rows, fully unrolled -> 16 outstanding 16B loads per thread.
// Total threads = NSPLIT * IN_F/4 = 262144 (1024 blocks x 256) -> high occ.
// ---------------------------------------------------------------------------
__global__ __launch_bounds__(256)
void wsum_partial_kernel(const float4* __restrict__ W4) {
    const int colgs = IN_F / 4;                       // 1024
    int tid   = blockIdx.x * blockDim.x + threadIdx.x;
    int colg  = tid & (colgs - 1);
    int split = tid >> 10;                            // tid / 1024 : 0..255
    const int rows = OUT_F / NSPLIT;                  // 16
    const float4* p = W4 + (size_t)(split * rows) * colgs + colg;

    float4 acc = make_float4(0.f, 0.f, 0.f, 0.f);
    #pragma unroll
    for (int r = 0; r < rows; ++r) {
        float4 v = p[(size_t)r * colgs];
        acc.x += v.x; acc.y += v.y; acc.z += v.z; acc.w += v.w;
    }
    reinterpret_cast<float4*>(g_partial)[split * colgs + colg] = acc;
}

// ---------------------------------------------------------------------------
// A2 (fused): finalize ws[j] = sum over splits of partials (4096 threads,
// coalesced column-major reads, partials are L2-resident), and block 0
// additionally reduces bias -> g_bsum.
// ---------------------------------------------------------------------------
__global__ __launch_bounds__(512)
void wsum_finalize_bias_kernel(const float* __restrict__ bias) {
    int j = blockIdx.x * blockDim.x + threadIdx.x;    // 0..IN_F-1  (8 blocks x 512)
    float s = 0.f;
    #pragma unroll 16
    for (int k = 0; k < NSPLIT; ++k)
        s += g_partial[k * IN_F + j];
    g_ws[j] = s;

    // Block 0 also computes the bias sum.
    if (blockIdx.x == 0) {
        __shared__ float sh[16];
        float b = 0.f;
        for (int i = threadIdx.x; i < OUT_F; i += blockDim.x)
            b += __ldg(&bias[i]);
        #pragma unroll
        for (int o = 16; o > 0; o >>= 1)
            b += __shfl_xor_sync(0xffffffffu, b, o);
        int lane = threadIdx.x & 31, warp = threadIdx.x >> 5;
        if (lane == 0) sh[warp] = b;
        __syncthreads();
        if (warp == 0) {
            float t = (lane < (int)(blockDim.x >> 5)) ? sh[lane] : 0.f;
            #pragma unroll
            for (int o = 16; o > 0; o >>= 1)
                t += __shfl_xor_sync(0xffffffffu, t, o);
            if (lane == 0) g_bsum = t;
        }
    }
}

// ---------------------------------------------------------------------------
// B: out[row] = dot(x[row], ws) + bsum. One warp per row.
// Each lane: 32 float4 loads of x (coalesced across the warp) + 32 float4
// loads of ws (L1-resident after first pass). Fixed shuffle-reduce order
// -> bitwise deterministic. Measured 77% DRAM SOL — near ceiling.
// ---------------------------------------------------------------------------
__global__ __launch_bounds__(256)
void rowdot_kernel(const float4* __restrict__ x4,
                   float* __restrict__ out) {
    int gwarp = (blockIdx.x * blockDim.x + threadIdx.x) >> 5;
    int lane  = threadIdx.x & 31;
    if (gwarp >= BATCH) return;

    const int colgs = IN_F / 4;                        // 1024
    const float4* xr  = x4 + (size_t)gwarp * colgs;
    const float4* ws4 = reinterpret_cast<const float4*>(g_ws);

    float acc = 0.f;
    #pragma unroll 8
    for (int i = lane; i < colgs; i += 32) {
        float4 xv = xr[i];
        float4 wv = __ldg(&ws4[i]);
        acc += xv.x * wv.x + xv.y * wv.y + xv.z * wv.z + xv.w * wv.w;
    }
    #pragma unroll
    for (int o = 16; o > 0; o >>= 1)
        acc += __shfl_xor_sync(0xffffffffu, acc, o);
    if (lane == 0)
        out[gwarp] = acc + g_bsum;
}

extern "C" void kernel_launch(void* const* d_in, const int* in_sizes, int n_in,
                              void* d_out, int out_size) {
    const float* x    = (const float*)d_in[0];   // [BATCH, IN_F]
    const float* W    = (const float*)d_in[1];   // [OUT_F, IN_F]
    const float* bias = (const float*)d_in[2];   // [OUT_F]
    float* out = (float*)d_out;                  // [BATCH, 1]

    (void)in_sizes; (void)n_in; (void)out_size;

    // A1: 262144 threads = 1024 blocks x 256
    wsum_partial_kernel<<<(NSPLIT * (IN_F / 4)) / 256, 256>>>(
        reinterpret_cast<const float4*>(W));

    // A2 fused with bias reduce: 4096 threads = 8 blocks x 512
    wsum_finalize_bias_kernel<<<IN_F / 512, 512>>>(bias);

    // B: one warp per row -> 16384 warps = 2048 blocks x 256 threads
    rowdot_kernel<<<(BATCH * 32) / 256, 256>>>(
        reinterpret_cast<const float4*>(x), out);
}

// round 8
// speedup vs baseline: 1.0997x; 1.0997x over previous
#include <cuda_runtime.h>

#define IN_F   4096
#define OUT_F  4096
#define BATCH  16384
#define NSPLIT 256         // row-splits for W column-sum partials

// Scratch (no device allocation allowed) — fully overwritten every launch
// sequence, so graph replays are deterministic.
__device__ float g_partial[NSPLIT * IN_F];   // 4 MB (L2-resident)
__device__ float g_ws[IN_F];
__device__ float g_bsum;

// ---------------------------------------------------------------------------
// A1: partial column sums of W.
// tid -> (split, colgroup-of-4). Consecutive threads hit consecutive float4s
// within a row -> perfectly coalesced. Each thread walks OUT_F/NSPLIT = 16
// rows. unroll 4 (NOT 16): limits MLP_p1 to curb cross-CTA L1tex-queue
// contention / CTA spread on this single-wave launch (B300 spread model).
// Total threads = NSPLIT * IN_F/4 = 262144 (1024 blocks x 256).
// ---------------------------------------------------------------------------
__global__ __launch_bounds__(256)
void wsum_partial_kernel(const float4* __restrict__ W4) {
    const int colgs = IN_F / 4;                       // 1024
    int tid   = blockIdx.x * blockDim.x + threadIdx.x;
    int colg  = tid & (colgs - 1);
    int split = tid >> 10;                            // 0..255
    const int rows = OUT_F / NSPLIT;                  // 16
    const float4* p = W4 + (size_t)(split * rows) * colgs + colg;

    float4 acc = make_float4(0.f, 0.f, 0.f, 0.f);
    #pragma unroll 4
    for (int r = 0; r < rows; ++r) {
        float4 v = p[(size_t)r * colgs];
        acc.x += v.x; acc.y += v.y; acc.z += v.z; acc.w += v.w;
    }
    reinterpret_cast<float4*>(g_partial)[split * colgs + colg] = acc;
}

// ---------------------------------------------------------------------------
// A2 (parallel finalize + bias): 128 blocks x 256 threads.
// Block b owns columns j = b*32 .. b*32+31. Thread = (group g = tid>>5,
// lane = tid&31); group g sums splits k in [g*32, g*32+32) for column
// j = b*32+lane (coalesced 128B rows of g_partial, L2-resident). Cross-group
// reduce in smem with a fixed order -> deterministic. Block 0 also reduces
// bias -> g_bsum.
// ---------------------------------------------------------------------------
__global__ __launch_bounds__(256)
void wsum_finalize_bias_kernel(const float* __restrict__ bias) {
    __shared__ float sh[256];
    int lane = threadIdx.x & 31;
    int g    = threadIdx.x >> 5;                      // 0..7
    int j    = blockIdx.x * 32 + lane;                // column

    float s = 0.f;
    #pragma unroll 8
    for (int k = g * 32; k < g * 32 + 32; ++k)
        s += g_partial[k * IN_F + j];
    sh[threadIdx.x] = s;
    __syncthreads();

    if (g == 0) {
        float t = 0.f;
        #pragma unroll
        for (int m = 0; m < 8; ++m)
            t += sh[m * 32 + lane];
        g_ws[j] = t;
    }

    // Block 0 additionally computes the bias sum (16 KB read).
    if (blockIdx.x == 0) {
        __syncthreads();
        float b = 0.f;
        #pragma unroll
        for (int i = threadIdx.x; i < OUT_F; i += 256)
            b += __ldg(&bias[i]);
        #pragma unroll
        for (int o = 16; o > 0; o >>= 1)
            b += __shfl_xor_sync(0xffffffffu, b, o);
        if (lane == 0) sh[g] = b;
        __syncthreads();
        if (threadIdx.x == 0) {
            float t = 0.f;
            #pragma unroll
            for (int m = 0; m < 8; ++m) t += sh[m];
            g_bsum = t;
        }
    }
}

// ---------------------------------------------------------------------------
// B: out[row] = dot(x[row], ws) + bsum. One warp per row.
// Each lane: 32 float4 loads of x (coalesced across the warp) + 32 float4
// loads of ws (L1-resident after first pass). Fixed shuffle-reduce order
// -> bitwise deterministic. Measured 44.6us @ 77% DRAM SOL — near ceiling.
// ---------------------------------------------------------------------------
__global__ __launch_bounds__(256)
void rowdot_kernel(const float4* __restrict__ x4,
                   float* __restrict__ out) {
    int gwarp = (blockIdx.x * blockDim.x + threadIdx.x) >> 5;
    int lane  = threadIdx.x & 31;
    if (gwarp >= BATCH) return;

    const int colgs = IN_F / 4;                        // 1024
    const float4* xr  = x4 + (size_t)gwarp * colgs;
    const float4* ws4 = reinterpret_cast<const float4*>(g_ws);

    float acc = 0.f;
    #pragma unroll 8
    for (int i = lane; i < colgs; i += 32) {
        float4 xv = xr[i];
        float4 wv = __ldg(&ws4[i]);
        acc += xv.x * wv.x + xv.y * wv.y + xv.z * wv.z + xv.w * wv.w;
    }
    #pragma unroll
    for (int o = 16; o > 0; o >>= 1)
        acc += __shfl_xor_sync(0xffffffffu, acc, o);
    if (lane == 0)
        out[gwarp] = acc + g_bsum;
}

extern "C" void kernel_launch(void* const* d_in, const int* in_sizes, int n_in,
                              void* d_out, int out_size) {
    const float* x    = (const float*)d_in[0];   // [BATCH, IN_F]
    const float* W    = (const float*)d_in[1];   // [OUT_F, IN_F]
    const float* bias = (const float*)d_in[2];   // [OUT_F]
    float* out = (float*)d_out;                  // [BATCH, 1]

    (void)in_sizes; (void)n_in; (void)out_size;

    // A1: 262144 threads = 1024 blocks x 256
    wsum_partial_kernel<<<(NSPLIT * (IN_F / 4)) / 256, 256>>>(
        reinterpret_cast<const float4*>(W));

    // A2: 128 blocks x 256 (32 columns/block, 8 split-groups)
    wsum_finalize_bias_kernel<<<IN_F / 32, 256>>>(bias);

    // B: one warp per row -> 16384 warps = 2048 blocks x 256 threads
    rowdot_kernel<<<(BATCH * 32) / 256, 256>>>(
        reinterpret_cast<const float4*>(x), out);
}